// round 1
// baseline (speedup 1.0000x reference)
#include <cuda_runtime.h>
#include <cuda_bf16.h>
#include <math.h>

#define N_NODES 50000
#define N_EDGES 800000
#define IN_DIM 512
#define HID_DIM 64
#define OUT_DIM 40

// ---------------- scratch (no allocations allowed) ----------------
__device__ float g_h1[N_NODES * HID_DIM];     // x @ W1
__device__ float g_agg1[N_NODES * HID_DIM];   // segment_sum layer 1
__device__ float g_h2[N_NODES * OUT_DIM];     // relu(agg1) @ W2
__device__ float g_agg2[N_NODES * OUT_DIM];   // segment_sum layer 2
__device__ int   g_src[N_EDGES];
__device__ int   g_dst[N_EDGES];
__device__ int   g_is64;

// ---------------- index dtype detection + conversion ----------------
// If the edge buffers are int64 (values < 50000 -> high 32-bit word == 0 for
// every element), the OR of odd words is 0. If int32, odd words are node ids
// (P(all 1024 sampled == 0) ~ 0).
__global__ void detect_idx_kernel(const unsigned int* __restrict__ buf) {
    unsigned v = 0;
    for (int i = threadIdx.x; i < 1024; i += 32) v |= buf[2 * i + 1];
#pragma unroll
    for (int o = 16; o; o >>= 1) v |= __shfl_xor_sync(0xFFFFFFFFu, v, o);
    if (threadIdx.x == 0) g_is64 = (v == 0) ? 1 : 0;
}

__global__ void cvt_idx_kernel(const unsigned int* __restrict__ bufA,
                               const unsigned int* __restrict__ bufB,
                               int n, int* __restrict__ outA, int* __restrict__ outB) {
    int i = blockIdx.x * blockDim.x + threadIdx.x;
    if (i >= n) return;
    int is64 = g_is64;
    outA[i] = (int)(is64 ? bufA[2 * i] : bufA[i]);
    outB[i] = (int)(is64 ? bufB[2 * i] : bufB[i]);
}

// ---------------- zeroing ----------------
__global__ void zero2_kernel(float4* a, int na4, float4* b, int nb4) {
    int i = blockIdx.x * blockDim.x + threadIdx.x;
    float4 z = make_float4(0.f, 0.f, 0.f, 0.f);
    if (i < na4) a[i] = z;
    if (i < nb4) b[i] = z;
}

// ---------------- GEMM1: H = X @ W1, [50000,512]x[512,64] ----------------
// BM=64, BN=64, BK=32 tile; 256 threads; 4x4 microtile per thread.
__global__ __launch_bounds__(256) void gemm1_kernel(
    const float* __restrict__ X, const float* __restrict__ W, float* __restrict__ H, int M) {
    __shared__ float xs[32][65];  // xs[k][m]
    __shared__ float ws[32][64];  // ws[k][n]
    const int block_row = blockIdx.x * 64;
    const int tid = threadIdx.x;
    const int tx = tid & 15, ty = tid >> 4;

    float acc[4][4];
#pragma unroll
    for (int i = 0; i < 4; i++)
#pragma unroll
        for (int j = 0; j < 4; j++) acc[i][j] = 0.f;

    for (int k0 = 0; k0 < IN_DIM; k0 += 32) {
        // load X tile: 64 rows x 32 cols = 512 float4, 2 per thread
#pragma unroll
        for (int j = 0; j < 2; j++) {
            int i = tid * 2 + j;
            int r = i >> 3, cv = i & 7;
            int grow = block_row + r;
            float4 v = make_float4(0.f, 0.f, 0.f, 0.f);
            if (grow < M)
                v = *(const float4*)(X + (size_t)grow * IN_DIM + k0 + cv * 4);
            xs[cv * 4 + 0][r] = v.x;
            xs[cv * 4 + 1][r] = v.y;
            xs[cv * 4 + 2][r] = v.z;
            xs[cv * 4 + 3][r] = v.w;
        }
        // load W tile: 32 rows x 64 cols = 512 float4, 2 per thread
#pragma unroll
        for (int j = 0; j < 2; j++) {
            int i = tid * 2 + j;
            int r = i >> 4, cv = i & 15;
            float4 v = *(const float4*)(W + (size_t)(k0 + r) * HID_DIM + cv * 4);
            *(float4*)&ws[r][cv * 4] = v;
        }
        __syncthreads();
#pragma unroll
        for (int k = 0; k < 32; k++) {
            float a[4], b[4];
#pragma unroll
            for (int i = 0; i < 4; i++) a[i] = xs[k][ty * 4 + i];
            float4 bv = *(float4*)&ws[k][tx * 4];
            b[0] = bv.x; b[1] = bv.y; b[2] = bv.z; b[3] = bv.w;
#pragma unroll
            for (int i = 0; i < 4; i++)
#pragma unroll
                for (int j = 0; j < 4; j++) acc[i][j] = fmaf(a[i], b[j], acc[i][j]);
        }
        __syncthreads();
    }
#pragma unroll
    for (int i = 0; i < 4; i++) {
        int row = block_row + ty * 4 + i;
        if (row < M) {
            float4 v = make_float4(acc[i][0], acc[i][1], acc[i][2], acc[i][3]);
            *(float4*)(H + (size_t)row * HID_DIM + tx * 4) = v;
        }
    }
}

// ---------------- vector atomic reduce ----------------
__device__ __forceinline__ void red_add_v4(float* p, float4 v) {
    asm volatile("red.global.add.v4.f32 [%0], {%1, %2, %3, %4};"
                 :: "l"(p), "f"(v.x), "f"(v.y), "f"(v.z), "f"(v.w)
                 : "memory");
}

// ---------------- scatter layer 1: 64 cols, 16 lanes/edge ----------------
__global__ __launch_bounds__(256) void scatter64_kernel(
    const float* __restrict__ h, const int* __restrict__ src,
    const int* __restrict__ dst, float* __restrict__ agg, int nE) {
    int idx = blockIdx.x * blockDim.x + threadIdx.x;
    int e = idx >> 4;
    int lane = idx & 15;
    if (e >= nE) return;
    int s = src[e], d = dst[e];
    float4 v = __ldg((const float4*)(h + (size_t)s * HID_DIM) + lane);
    red_add_v4((float*)((float4*)(agg + (size_t)d * HID_DIM) + lane), v);
}

// ---------------- GEMM2 fused relu: H2 = relu(A) @ W2, [50000,64]x[64,40] ----
__global__ __launch_bounds__(256) void gemm2_kernel(
    const float* __restrict__ A, const float* __restrict__ W2,
    float* __restrict__ H2, int M) {
    __shared__ float as[64][65];
    __shared__ float ws[64][40];
    const int base = blockIdx.x * 64;
    const int tid = threadIdx.x;

    // load A tile (with relu): 64x64 = 1024 float4, 4 per thread
#pragma unroll
    for (int j = 0; j < 4; j++) {
        int i = tid * 4 + j;
        int r = i >> 4, cv = i & 15;
        int grow = base + r;
        float4 v = make_float4(0.f, 0.f, 0.f, 0.f);
        if (grow < M) v = *(const float4*)(A + (size_t)grow * HID_DIM + cv * 4);
        as[r][cv * 4 + 0] = fmaxf(v.x, 0.f);
        as[r][cv * 4 + 1] = fmaxf(v.y, 0.f);
        as[r][cv * 4 + 2] = fmaxf(v.z, 0.f);
        as[r][cv * 4 + 3] = fmaxf(v.w, 0.f);
    }
    // load W2: 64x40 = 2560 floats, 10 per thread
    for (int i = tid; i < 64 * 40; i += 256) {
        ws[i / 40][i % 40] = W2[i];
    }
    __syncthreads();

    int r = tid >> 2;           // 0..63
    int cseg = (tid & 3) * 10;  // 0,10,20,30
    float accv[10];
#pragma unroll
    for (int j = 0; j < 10; j++) accv[j] = 0.f;
#pragma unroll
    for (int k = 0; k < 64; k++) {
        float a = as[r][k];
#pragma unroll
        for (int j = 0; j < 10; j++) accv[j] = fmaf(a, ws[k][cseg + j], accv[j]);
    }
    int row = base + r;
    if (row < M) {
        float* o = H2 + (size_t)row * OUT_DIM + cseg;
#pragma unroll
        for (int j = 0; j < 10; j++) o[j] = accv[j];
    }
}

// ---------------- scatter layer 2: 40 cols, 10 lanes/edge ----------------
__global__ __launch_bounds__(256) void scatter40_kernel(
    const float* __restrict__ h, const int* __restrict__ src,
    const int* __restrict__ dst, float* __restrict__ agg, int nE) {
    int idx = blockIdx.x * blockDim.x + threadIdx.x;
    int e = idx / 10;
    int lane = idx - e * 10;
    if (e >= nE) return;
    int s = src[e], d = dst[e];
    float4 v = __ldg((const float4*)(h + (size_t)s * OUT_DIM) + lane);
    red_add_v4((float*)((float4*)(agg + (size_t)d * OUT_DIM) + lane), v);
}

// ---------------- log_softmax: one warp per row ----------------
__global__ __launch_bounds__(256) void lsm_kernel(
    const float* __restrict__ A, float* __restrict__ out, int M) {
    int gwarp = (blockIdx.x * blockDim.x + threadIdx.x) >> 5;
    int lane = threadIdx.x & 31;
    if (gwarp >= M) return;
    const float* row = A + (size_t)gwarp * OUT_DIM;
    float e0 = row[lane];
    float e1 = (lane < 8) ? row[lane + 32] : -INFINITY;
    float m = fmaxf(e0, e1);
#pragma unroll
    for (int o = 16; o; o >>= 1) m = fmaxf(m, __shfl_xor_sync(0xFFFFFFFFu, m, o));
    float s = __expf(e0 - m) + ((lane < 8) ? __expf(e1 - m) : 0.f);
#pragma unroll
    for (int o = 16; o; o >>= 1) s += __shfl_xor_sync(0xFFFFFFFFu, s, o);
    float l = m + __logf(s);
    float* orow = out + (size_t)gwarp * OUT_DIM;
    orow[lane] = e0 - l;
    if (lane < 8) orow[lane + 32] = e1 - l;
}

// ---------------- launch ----------------
extern "C" void kernel_launch(void* const* d_in, const int* in_sizes, int n_in,
                              void* d_out, int out_size) {
    const float* x  = (const float*)d_in[0];
    const unsigned int* srcbuf = (const unsigned int*)d_in[1];
    const unsigned int* dstbuf = (const unsigned int*)d_in[2];
    const float* W1 = (const float*)d_in[3];
    const float* W2 = (const float*)d_in[4];
    float* out = (float*)d_out;

    const int M = in_sizes[0] / IN_DIM;      // 50000
    const int nE = in_sizes[1];              // 800000

    float* h1   = nullptr; cudaGetSymbolAddress((void**)&h1,   g_h1);
    float* agg1 = nullptr; cudaGetSymbolAddress((void**)&agg1, g_agg1);
    float* h2   = nullptr; cudaGetSymbolAddress((void**)&h2,   g_h2);
    float* agg2 = nullptr; cudaGetSymbolAddress((void**)&agg2, g_agg2);
    int* srci   = nullptr; cudaGetSymbolAddress((void**)&srci, g_src);
    int* dsti   = nullptr; cudaGetSymbolAddress((void**)&dsti, g_dst);

    // 1. detect index dtype + convert to int32
    detect_idx_kernel<<<1, 32>>>(srcbuf);
    cvt_idx_kernel<<<(nE + 255) / 256, 256>>>(srcbuf, dstbuf, nE, srci, dsti);

    // 2. zero accumulators
    int na4 = M * HID_DIM / 4, nb4 = M * OUT_DIM / 4;
    zero2_kernel<<<(na4 + 255) / 256, 256>>>((float4*)agg1, na4, (float4*)agg2, nb4);

    // 3. GEMM1
    gemm1_kernel<<<(M + 63) / 64, 256>>>(x, W1, h1, M);

    // 4. scatter layer 1
    {
        long long t = (long long)nE * 16;
        scatter64_kernel<<<(unsigned)((t + 255) / 256), 256>>>(h1, srci, dsti, agg1, nE);
    }

    // 5. GEMM2 (+relu)
    gemm2_kernel<<<(M + 63) / 64, 256>>>(agg1, W2, h2, M);

    // 6. scatter layer 2
    {
        long long t = (long long)nE * 10;
        scatter40_kernel<<<(unsigned)((t + 255) / 256), 256>>>(h2, srci, dsti, agg2, nE);
    }

    // 7. log_softmax
    lsm_kernel<<<(M * 32 + 255) / 256, 256>>>(agg2, out, M);
}

// round 2
// speedup vs baseline: 1.4985x; 1.4985x over previous
#include <cuda_runtime.h>
#include <cuda_bf16.h>
#include <math.h>

#define N_NODES 50000
#define N_EDGES 800000
#define IN_DIM 512
#define HID_DIM 64
#define OUT_DIM 40

// ---------------- scratch (no allocations allowed) ----------------
__device__ float g_h1[N_NODES * HID_DIM];     // x @ W1
__device__ float g_agg1[N_NODES * HID_DIM];   // segment_sum layer 1
__device__ float g_h2[N_NODES * OUT_DIM];     // relu(agg1) @ W2
__device__ float g_agg2[N_NODES * OUT_DIM];   // segment_sum layer 2
__device__ int   g_src[N_EDGES];
__device__ int   g_dst[N_EDGES];
__device__ int   g_is64;

// ---------------- index dtype detection + conversion ----------------
__global__ void detect_idx_kernel(const unsigned int* __restrict__ buf) {
    unsigned v = 0;
    for (int i = threadIdx.x; i < 1024; i += 32) v |= buf[2 * i + 1];
#pragma unroll
    for (int o = 16; o; o >>= 1) v |= __shfl_xor_sync(0xFFFFFFFFu, v, o);
    if (threadIdx.x == 0) g_is64 = (v == 0) ? 1 : 0;
}

__global__ void cvt_idx_kernel(const unsigned int* __restrict__ bufA,
                               const unsigned int* __restrict__ bufB,
                               int n, int* __restrict__ outA, int* __restrict__ outB) {
    int i = blockIdx.x * blockDim.x + threadIdx.x;
    if (i >= n) return;
    int is64 = g_is64;
    outA[i] = (int)(is64 ? bufA[2 * i] : bufA[i]);
    outB[i] = (int)(is64 ? bufB[2 * i] : bufB[i]);
}

// ---------------- zeroing ----------------
__global__ void zero2_kernel(float4* a, int na4, float4* b, int nb4) {
    int i = blockIdx.x * blockDim.x + threadIdx.x;
    float4 z = make_float4(0.f, 0.f, 0.f, 0.f);
    if (i < na4) a[i] = z;
    if (i < nb4) b[i] = z;
}

// ---------------- GEMM1 (tf32 tensor cores): H = X @ W1 ----------------
// [50000,512] x [512,64]. Block tile 128x64, BK=32, 8 warps (warp tile 32x32),
// 2-stage cp.async pipeline. mma.sync.m16n8k8.tf32, fp32 accumulate.
#define G1_BM 128
#define G1_BN 64
#define G1_BK 32
#define G1_ASTRIDE 36   // BK + 4 pad  -> conflict-free fragment loads
#define G1_BSTRIDE 72   // BN + 8 pad  -> conflict-free fragment loads
#define G1_A_ELEMS (G1_BM * G1_ASTRIDE)
#define G1_B_ELEMS (G1_BK * G1_BSTRIDE)
#define G1_SMEM_BYTES ((2 * G1_A_ELEMS + 2 * G1_B_ELEMS) * 4)

__device__ __forceinline__ void cp_async16(void* sdst, const void* gsrc) {
    unsigned s = (unsigned)__cvta_generic_to_shared(sdst);
    asm volatile("cp.async.cg.shared.global [%0], [%1], 16;" :: "r"(s), "l"(gsrc));
}
__device__ __forceinline__ unsigned f2tf32(float f) {
    unsigned u;
    asm("cvt.rna.tf32.f32 %0, %1;" : "=r"(u) : "f"(f));
    return u;
}
__device__ __forceinline__ void mma_tf32(float* d, const unsigned* a, const unsigned* b) {
    asm volatile(
        "mma.sync.aligned.m16n8k8.row.col.f32.tf32.tf32.f32 "
        "{%0,%1,%2,%3}, {%4,%5,%6,%7}, {%8,%9}, {%0,%1,%2,%3};"
        : "+f"(d[0]), "+f"(d[1]), "+f"(d[2]), "+f"(d[3])
        : "r"(a[0]), "r"(a[1]), "r"(a[2]), "r"(a[3]), "r"(b[0]), "r"(b[1]));
}

__global__ __launch_bounds__(256) void gemm1_tf32_kernel(
    const float* __restrict__ X, const float* __restrict__ W,
    float* __restrict__ H, int M) {
    extern __shared__ float smem[];
    float* As = smem;                     // [2][BM][ASTRIDE]
    float* Bs = smem + 2 * G1_A_ELEMS;    // [2][BK][BSTRIDE]

    const int tid = threadIdx.x;
    const int blockM = blockIdx.x * G1_BM;
    const int lane = tid & 31, warp = tid >> 5;
    const int g = lane >> 2, t4 = lane & 3;
    const int wm = warp & 3, wn = warp >> 2;   // 4 warps in M, 2 in N

    // chunk loader: A = 1024 float4 (4/thread), B = 512 float4 (2/thread)
    auto load_chunk = [&](int st, int it) {
        const int k0 = it * G1_BK;
        float* as = As + st * G1_A_ELEMS;
        float* bs = Bs + st * G1_B_ELEMS;
#pragma unroll
        for (int j = 0; j < 4; j++) {
            int idx = tid + 256 * j;          // 0..1023
            int r = idx >> 3, cv = idx & 7;
            int grow = blockM + r;
            if (grow > M - 1) grow = M - 1;   // clamp; masked at store
            cp_async16(as + r * G1_ASTRIDE + cv * 4,
                       X + (size_t)grow * IN_DIM + k0 + cv * 4);
        }
#pragma unroll
        for (int j = 0; j < 2; j++) {
            int idx = tid + 256 * j;          // 0..511
            int r = idx >> 4, cv = idx & 15;
            cp_async16(bs + r * G1_BSTRIDE + cv * 4,
                       W + (size_t)(k0 + r) * HID_DIM + cv * 4);
        }
    };

    float acc[2][4][4];
#pragma unroll
    for (int mi = 0; mi < 2; mi++)
#pragma unroll
        for (int nj = 0; nj < 4; nj++)
#pragma unroll
            for (int q = 0; q < 4; q++) acc[mi][nj][q] = 0.f;

    const int NIT = IN_DIM / G1_BK;  // 16
    load_chunk(0, 0);
    asm volatile("cp.async.commit_group;");

    for (int it = 0; it < NIT; ++it) {
        if (it + 1 < NIT) {
            load_chunk((it + 1) & 1, it + 1);
            asm volatile("cp.async.commit_group;");
            asm volatile("cp.async.wait_group 1;");
        } else {
            asm volatile("cp.async.wait_group 0;");
        }
        __syncthreads();

        const float* as = As + (it & 1) * G1_A_ELEMS;
        const float* bs = Bs + (it & 1) * G1_B_ELEMS;
#pragma unroll
        for (int ks = 0; ks < 4; ks++) {
            const int kk = ks * 8;
            unsigned a[2][4];
#pragma unroll
            for (int mi = 0; mi < 2; mi++) {
                int rm = wm * 32 + mi * 16;
                a[mi][0] = f2tf32(as[(rm + g) * G1_ASTRIDE + kk + t4]);
                a[mi][1] = f2tf32(as[(rm + g + 8) * G1_ASTRIDE + kk + t4]);
                a[mi][2] = f2tf32(as[(rm + g) * G1_ASTRIDE + kk + t4 + 4]);
                a[mi][3] = f2tf32(as[(rm + g + 8) * G1_ASTRIDE + kk + t4 + 4]);
            }
            unsigned b[4][2];
#pragma unroll
            for (int nj = 0; nj < 4; nj++) {
                int nb = wn * 32 + nj * 8 + g;
                b[nj][0] = f2tf32(bs[(kk + t4) * G1_BSTRIDE + nb]);
                b[nj][1] = f2tf32(bs[(kk + t4 + 4) * G1_BSTRIDE + nb]);
            }
#pragma unroll
            for (int mi = 0; mi < 2; mi++)
#pragma unroll
                for (int nj = 0; nj < 4; nj++) mma_tf32(acc[mi][nj], a[mi], b[nj]);
        }
        __syncthreads();
    }

    // store: c0,c1 -> (row, col..col+1), c2,c3 -> (row+8, col..col+1)
#pragma unroll
    for (int mi = 0; mi < 2; mi++) {
        int row0 = blockM + wm * 32 + mi * 16 + g;
        int row1 = row0 + 8;
#pragma unroll
        for (int nj = 0; nj < 4; nj++) {
            int col = wn * 32 + nj * 8 + t4 * 2;
            if (row0 < M)
                *(float2*)(H + (size_t)row0 * HID_DIM + col) =
                    make_float2(acc[mi][nj][0], acc[mi][nj][1]);
            if (row1 < M)
                *(float2*)(H + (size_t)row1 * HID_DIM + col) =
                    make_float2(acc[mi][nj][2], acc[mi][nj][3]);
        }
    }
}

// ---------------- vector atomic reduce ----------------
__device__ __forceinline__ void red_add_v4(float* p, float4 v) {
    asm volatile("red.global.add.v4.f32 [%0], {%1, %2, %3, %4};"
                 :: "l"(p), "f"(v.x), "f"(v.y), "f"(v.z), "f"(v.w)
                 : "memory");
}

// ---------------- scatter layer 1: 64 cols, 16 lanes/edge ----------------
__global__ __launch_bounds__(256) void scatter64_kernel(
    const float* __restrict__ h, const int* __restrict__ src,
    const int* __restrict__ dst, float* __restrict__ agg, int nE) {
    int idx = blockIdx.x * blockDim.x + threadIdx.x;
    int e = idx >> 4;
    int lane = idx & 15;
    if (e >= nE) return;
    int s = src[e], d = dst[e];
    float4 v = __ldg((const float4*)(h + (size_t)s * HID_DIM) + lane);
    red_add_v4((float*)((float4*)(agg + (size_t)d * HID_DIM) + lane), v);
}

// ---------------- GEMM2 fused relu: H2 = relu(A) @ W2 ----------------
__global__ __launch_bounds__(256) void gemm2_kernel(
    const float* __restrict__ A, const float* __restrict__ W2,
    float* __restrict__ H2, int M) {
    __shared__ float as[64][65];
    __shared__ float ws[64][40];
    const int base = blockIdx.x * 64;
    const int tid = threadIdx.x;

#pragma unroll
    for (int j = 0; j < 4; j++) {
        int i = tid * 4 + j;
        int r = i >> 4, cv = i & 15;
        int grow = base + r;
        float4 v = make_float4(0.f, 0.f, 0.f, 0.f);
        if (grow < M) v = *(const float4*)(A + (size_t)grow * HID_DIM + cv * 4);
        as[r][cv * 4 + 0] = fmaxf(v.x, 0.f);
        as[r][cv * 4 + 1] = fmaxf(v.y, 0.f);
        as[r][cv * 4 + 2] = fmaxf(v.z, 0.f);
        as[r][cv * 4 + 3] = fmaxf(v.w, 0.f);
    }
    for (int i = tid; i < 64 * 40; i += 256) {
        ws[i / 40][i % 40] = W2[i];
    }
    __syncthreads();

    int r = tid >> 2;
    int cseg = (tid & 3) * 10;
    float accv[10];
#pragma unroll
    for (int j = 0; j < 10; j++) accv[j] = 0.f;
#pragma unroll
    for (int k = 0; k < 64; k++) {
        float a = as[r][k];
#pragma unroll
        for (int j = 0; j < 10; j++) accv[j] = fmaf(a, ws[k][cseg + j], accv[j]);
    }
    int row = base + r;
    if (row < M) {
        float* o = H2 + (size_t)row * OUT_DIM + cseg;
#pragma unroll
        for (int j = 0; j < 10; j++) o[j] = accv[j];
    }
}

// ---------------- scatter layer 2: 40 cols, 10 lanes/edge ----------------
__global__ __launch_bounds__(256) void scatter40_kernel(
    const float* __restrict__ h, const int* __restrict__ src,
    const int* __restrict__ dst, float* __restrict__ agg, int nE) {
    int idx = blockIdx.x * blockDim.x + threadIdx.x;
    int e = idx / 10;
    int lane = idx - e * 10;
    if (e >= nE) return;
    int s = src[e], d = dst[e];
    float4 v = __ldg((const float4*)(h + (size_t)s * OUT_DIM) + lane);
    red_add_v4((float*)((float4*)(agg + (size_t)d * OUT_DIM) + lane), v);
}

// ---------------- log_softmax: one warp per row ----------------
__global__ __launch_bounds__(256) void lsm_kernel(
    const float* __restrict__ A, float* __restrict__ out, int M) {
    int gwarp = (blockIdx.x * blockDim.x + threadIdx.x) >> 5;
    int lane = threadIdx.x & 31;
    if (gwarp >= M) return;
    const float* row = A + (size_t)gwarp * OUT_DIM;
    float e0 = row[lane];
    float e1 = (lane < 8) ? row[lane + 32] : -INFINITY;
    float m = fmaxf(e0, e1);
#pragma unroll
    for (int o = 16; o; o >>= 1) m = fmaxf(m, __shfl_xor_sync(0xFFFFFFFFu, m, o));
    float s = __expf(e0 - m) + ((lane < 8) ? __expf(e1 - m) : 0.f);
#pragma unroll
    for (int o = 16; o; o >>= 1) s += __shfl_xor_sync(0xFFFFFFFFu, s, o);
    float l = m + __logf(s);
    float* orow = out + (size_t)gwarp * OUT_DIM;
    orow[lane] = e0 - l;
    if (lane < 8) orow[lane + 32] = e1 - l;
}

// ---------------- launch ----------------
extern "C" void kernel_launch(void* const* d_in, const int* in_sizes, int n_in,
                              void* d_out, int out_size) {
    const float* x  = (const float*)d_in[0];
    const unsigned int* srcbuf = (const unsigned int*)d_in[1];
    const unsigned int* dstbuf = (const unsigned int*)d_in[2];
    const float* W1 = (const float*)d_in[3];
    const float* W2 = (const float*)d_in[4];
    float* out = (float*)d_out;

    const int M = in_sizes[0] / IN_DIM;      // 50000
    const int nE = in_sizes[1];              // 800000

    float* h1   = nullptr; cudaGetSymbolAddress((void**)&h1,   g_h1);
    float* agg1 = nullptr; cudaGetSymbolAddress((void**)&agg1, g_agg1);
    float* h2   = nullptr; cudaGetSymbolAddress((void**)&h2,   g_h2);
    float* agg2 = nullptr; cudaGetSymbolAddress((void**)&agg2, g_agg2);
    int* srci   = nullptr; cudaGetSymbolAddress((void**)&srci, g_src);
    int* dsti   = nullptr; cudaGetSymbolAddress((void**)&dsti, g_dst);

    cudaFuncSetAttribute(gemm1_tf32_kernel,
                         cudaFuncAttributeMaxDynamicSharedMemorySize, G1_SMEM_BYTES);

    // 1. detect index dtype + convert to int32
    detect_idx_kernel<<<1, 32>>>(srcbuf);
    cvt_idx_kernel<<<(nE + 255) / 256, 256>>>(srcbuf, dstbuf, nE, srci, dsti);

    // 2. zero accumulators
    int na4 = M * HID_DIM / 4, nb4 = M * OUT_DIM / 4;
    zero2_kernel<<<(na4 + 255) / 256, 256>>>((float4*)agg1, na4, (float4*)agg2, nb4);

    // 3. GEMM1 (tf32 tensor cores)
    gemm1_tf32_kernel<<<(M + G1_BM - 1) / G1_BM, 256, G1_SMEM_BYTES>>>(x, W1, h1, M);

    // 4. scatter layer 1
    {
        long long t = (long long)nE * 16;
        scatter64_kernel<<<(unsigned)((t + 255) / 256), 256>>>(h1, srci, dsti, agg1, nE);
    }

    // 5. GEMM2 (+relu)
    gemm2_kernel<<<(M + 63) / 64, 256>>>(agg1, W2, h2, M);

    // 6. scatter layer 2
    {
        long long t = (long long)nE * 10;
        scatter40_kernel<<<(unsigned)((t + 255) / 256), 256>>>(h2, srci, dsti, agg2, nE);
    }

    // 7. log_softmax
    lsm_kernel<<<(M * 32 + 255) / 256, 256>>>(agg2, out, M);
}

// round 3
// speedup vs baseline: 1.7267x; 1.1523x over previous
#include <cuda_runtime.h>
#include <cuda_bf16.h>
#include <math.h>

#define N_NODES 50000
#define N_EDGES 800000
#define IN_DIM 512
#define HID_DIM 64
#define OUT_DIM 40
#define SCAN_NB ((N_NODES + 255) / 256)   // 196

// ---------------- scratch (no allocations allowed) ----------------
__device__ float g_h1[N_NODES * HID_DIM];     // x @ W1
__device__ float g_agg1[N_NODES * HID_DIM];   // segment_sum layer 1
__device__ float g_h2[N_NODES * OUT_DIM];     // relu(agg1) @ W2
__device__ float g_agg2[N_NODES * OUT_DIM];   // segment_sum layer 2
__device__ int   g_src[N_EDGES];
__device__ int   g_dst[N_EDGES];
__device__ int   g_csr[N_EDGES];              // src ids grouped by dst
__device__ int   g_cnt[N_NODES];              // per-dst degree
__device__ int   g_rowstart[N_NODES + 1];
__device__ int   g_cursor[N_NODES];
__device__ int   g_bsum[SCAN_NB];
__device__ int   g_boff[SCAN_NB];
__device__ int   g_is64;

// ---------------- index dtype detection ----------------
__global__ void detect_idx_kernel(const unsigned int* __restrict__ buf) {
    unsigned v = 0;
    for (int i = threadIdx.x; i < 1024; i += 32) v |= buf[2 * i + 1];
#pragma unroll
    for (int o = 16; o; o >>= 1) v |= __shfl_xor_sync(0xFFFFFFFFu, v, o);
    if (threadIdx.x == 0) g_is64 = (v == 0) ? 1 : 0;
}

__global__ void zero_cnt_kernel(int* __restrict__ cnt, int n) {
    int i = blockIdx.x * blockDim.x + threadIdx.x;
    if (i < n) cnt[i] = 0;
}

// convert indices to int32 + histogram destinations
__global__ void cvt_hist_kernel(const unsigned int* __restrict__ bufA,
                                const unsigned int* __restrict__ bufB,
                                int n, int* __restrict__ outA, int* __restrict__ outB,
                                int* __restrict__ cnt) {
    int i = blockIdx.x * blockDim.x + threadIdx.x;
    if (i >= n) return;
    int is64 = g_is64;
    int s = (int)(is64 ? bufA[2 * i] : bufA[i]);
    int d = (int)(is64 ? bufB[2 * i] : bufB[i]);
    outA[i] = s;
    outB[i] = d;
    atomicAdd(&cnt[d], 1);
}

// ---------------- 3-kernel exclusive scan over g_cnt ----------------
__global__ void scan1_kernel(const int* __restrict__ cnt, int n, int* __restrict__ bsum) {
    __shared__ int sh[256];
    int i = blockIdx.x * 256 + threadIdx.x;
    int v = (i < n) ? cnt[i] : 0;
    sh[threadIdx.x] = v;
    __syncthreads();
    for (int off = 128; off; off >>= 1) {
        if (threadIdx.x < off) sh[threadIdx.x] += sh[threadIdx.x + off];
        __syncthreads();
    }
    if (threadIdx.x == 0) bsum[blockIdx.x] = sh[0];
}

__global__ void scan2_kernel(const int* __restrict__ bsum, int nb, int* __restrict__ boff) {
    __shared__ int sh[256];
    int t = threadIdx.x;
    int v = (t < nb) ? bsum[t] : 0;
    sh[t] = v;
    __syncthreads();
#pragma unroll
    for (int off = 1; off < 256; off <<= 1) {
        int x = (t >= off) ? sh[t - off] : 0;
        __syncthreads();
        sh[t] += x;
        __syncthreads();
    }
    if (t < nb) boff[t] = sh[t] - v;  // exclusive
}

__global__ void scan3_kernel(const int* __restrict__ cnt, int n, int nE,
                             const int* __restrict__ boff,
                             int* __restrict__ rowstart, int* __restrict__ cursor) {
    __shared__ int sh[256];
    int t = threadIdx.x;
    int i = blockIdx.x * 256 + t;
    int v = (i < n) ? cnt[i] : 0;
    sh[t] = v;
    __syncthreads();
#pragma unroll
    for (int off = 1; off < 256; off <<= 1) {
        int x = (t >= off) ? sh[t - off] : 0;
        __syncthreads();
        sh[t] += x;
        __syncthreads();
    }
    if (i < n) {
        int ex = sh[t] - v + boff[blockIdx.x];
        rowstart[i] = ex;
        cursor[i] = ex;
    }
    if (i == 0) rowstart[n] = nE;
}

__global__ void fill_kernel(const int* __restrict__ srci, const int* __restrict__ dsti,
                            int nE, int* __restrict__ cursor, int* __restrict__ csr) {
    int e = blockIdx.x * blockDim.x + threadIdx.x;
    if (e >= nE) return;
    int pos = atomicAdd(&cursor[dsti[e]], 1);
    csr[pos] = srci[e];
}

// ---------------- GEMM1 (tf32 tensor cores): H = X @ W1 ----------------
#define G1_BM 128
#define G1_BN 64
#define G1_BK 32
#define G1_ASTRIDE 36
#define G1_BSTRIDE 72
#define G1_A_ELEMS (G1_BM * G1_ASTRIDE)
#define G1_B_ELEMS (G1_BK * G1_BSTRIDE)
#define G1_SMEM_BYTES ((2 * G1_A_ELEMS + 2 * G1_B_ELEMS) * 4)

__device__ __forceinline__ void cp_async16(void* sdst, const void* gsrc) {
    unsigned s = (unsigned)__cvta_generic_to_shared(sdst);
    asm volatile("cp.async.cg.shared.global [%0], [%1], 16;" :: "r"(s), "l"(gsrc));
}
__device__ __forceinline__ void mma_tf32(float* d, const unsigned* a, const unsigned* b) {
    asm volatile(
        "mma.sync.aligned.m16n8k8.row.col.f32.tf32.tf32.f32 "
        "{%0,%1,%2,%3}, {%4,%5,%6,%7}, {%8,%9}, {%0,%1,%2,%3};"
        : "+f"(d[0]), "+f"(d[1]), "+f"(d[2]), "+f"(d[3])
        : "r"(a[0]), "r"(a[1]), "r"(a[2]), "r"(a[3]), "r"(b[0]), "r"(b[1]));
}

__global__ __launch_bounds__(256) void gemm1_tf32_kernel(
    const float* __restrict__ X, const float* __restrict__ W,
    float* __restrict__ H, int M) {
    extern __shared__ float smem[];
    float* As = smem;
    float* Bs = smem + 2 * G1_A_ELEMS;

    const int tid = threadIdx.x;
    const int blockM = blockIdx.x * G1_BM;
    const int lane = tid & 31, warp = tid >> 5;
    const int g = lane >> 2, t4 = lane & 3;
    const int wm = warp & 3, wn = warp >> 2;

    auto load_chunk = [&](int st, int it) {
        const int k0 = it * G1_BK;
        float* as = As + st * G1_A_ELEMS;
        float* bs = Bs + st * G1_B_ELEMS;
#pragma unroll
        for (int j = 0; j < 4; j++) {
            int idx = tid + 256 * j;
            int r = idx >> 3, cv = idx & 7;
            int grow = blockM + r;
            if (grow > M - 1) grow = M - 1;
            cp_async16(as + r * G1_ASTRIDE + cv * 4,
                       X + (size_t)grow * IN_DIM + k0 + cv * 4);
        }
#pragma unroll
        for (int j = 0; j < 2; j++) {
            int idx = tid + 256 * j;
            int r = idx >> 4, cv = idx & 15;
            cp_async16(bs + r * G1_BSTRIDE + cv * 4,
                       W + (size_t)(k0 + r) * HID_DIM + cv * 4);
        }
    };

    float acc[2][4][4];
#pragma unroll
    for (int mi = 0; mi < 2; mi++)
#pragma unroll
        for (int nj = 0; nj < 4; nj++)
#pragma unroll
            for (int q = 0; q < 4; q++) acc[mi][nj][q] = 0.f;

    const int NIT = IN_DIM / G1_BK;
    load_chunk(0, 0);
    asm volatile("cp.async.commit_group;");

    for (int it = 0; it < NIT; ++it) {
        if (it + 1 < NIT) {
            load_chunk((it + 1) & 1, it + 1);
            asm volatile("cp.async.commit_group;");
            asm volatile("cp.async.wait_group 1;");
        } else {
            asm volatile("cp.async.wait_group 0;");
        }
        __syncthreads();

        const float* as = As + (it & 1) * G1_A_ELEMS;
        const float* bs = Bs + (it & 1) * G1_B_ELEMS;
#pragma unroll
        for (int ks = 0; ks < 4; ks++) {
            const int kk = ks * 8;
            unsigned a[2][4];
#pragma unroll
            for (int mi = 0; mi < 2; mi++) {
                int rm = wm * 32 + mi * 16;
                a[mi][0] = __float_as_uint(as[(rm + g) * G1_ASTRIDE + kk + t4]);
                a[mi][1] = __float_as_uint(as[(rm + g + 8) * G1_ASTRIDE + kk + t4]);
                a[mi][2] = __float_as_uint(as[(rm + g) * G1_ASTRIDE + kk + t4 + 4]);
                a[mi][3] = __float_as_uint(as[(rm + g + 8) * G1_ASTRIDE + kk + t4 + 4]);
            }
            unsigned b[4][2];
#pragma unroll
            for (int nj = 0; nj < 4; nj++) {
                int nb = wn * 32 + nj * 8 + g;
                b[nj][0] = __float_as_uint(bs[(kk + t4) * G1_BSTRIDE + nb]);
                b[nj][1] = __float_as_uint(bs[(kk + t4 + 4) * G1_BSTRIDE + nb]);
            }
#pragma unroll
            for (int mi = 0; mi < 2; mi++)
#pragma unroll
                for (int nj = 0; nj < 4; nj++) mma_tf32(acc[mi][nj], a[mi], b[nj]);
        }
        __syncthreads();
    }

#pragma unroll
    for (int mi = 0; mi < 2; mi++) {
        int row0 = blockM + wm * 32 + mi * 16 + g;
        int row1 = row0 + 8;
#pragma unroll
        for (int nj = 0; nj < 4; nj++) {
            int col = wn * 32 + nj * 8 + t4 * 2;
            if (row0 < M)
                *(float2*)(H + (size_t)row0 * HID_DIM + col) =
                    make_float2(acc[mi][nj][0], acc[mi][nj][1]);
            if (row1 < M)
                *(float2*)(H + (size_t)row1 * HID_DIM + col) =
                    make_float2(acc[mi][nj][2], acc[mi][nj][3]);
        }
    }
}

// ---------------- gather aggregation, 64 cols: 16 threads/node ----------------
__global__ __launch_bounds__(256) void agg64_kernel(
    const float* __restrict__ h, const int* __restrict__ rowstart,
    const int* __restrict__ csr, float* __restrict__ agg, int nNodes) {
    int idx = blockIdx.x * blockDim.x + threadIdx.x;
    int node = idx >> 4;
    int c = idx & 15;
    if (node >= nNodes) return;
    int j = rowstart[node];
    int end = rowstart[node + 1];
    float4 acc = make_float4(0.f, 0.f, 0.f, 0.f);
    for (; j + 1 < end; j += 2) {
        int s0 = csr[j], s1 = csr[j + 1];
        float4 v0 = __ldg((const float4*)(h + (size_t)s0 * HID_DIM) + c);
        float4 v1 = __ldg((const float4*)(h + (size_t)s1 * HID_DIM) + c);
        acc.x += v0.x + v1.x; acc.y += v0.y + v1.y;
        acc.z += v0.z + v1.z; acc.w += v0.w + v1.w;
    }
    if (j < end) {
        int s0 = csr[j];
        float4 v0 = __ldg((const float4*)(h + (size_t)s0 * HID_DIM) + c);
        acc.x += v0.x; acc.y += v0.y; acc.z += v0.z; acc.w += v0.w;
    }
    ((float4*)(agg + (size_t)node * HID_DIM))[c] = acc;
}

// ---------------- gather aggregation, 40 cols: 10 threads/node ----------------
__global__ __launch_bounds__(256) void agg40_kernel(
    const float* __restrict__ h, const int* __restrict__ rowstart,
    const int* __restrict__ csr, float* __restrict__ agg, int nNodes) {
    int idx = blockIdx.x * blockDim.x + threadIdx.x;
    int node = idx / 10;
    int c = idx - node * 10;
    if (node >= nNodes) return;
    int j = rowstart[node];
    int end = rowstart[node + 1];
    float4 acc = make_float4(0.f, 0.f, 0.f, 0.f);
    for (; j + 1 < end; j += 2) {
        int s0 = csr[j], s1 = csr[j + 1];
        float4 v0 = __ldg((const float4*)(h + (size_t)s0 * OUT_DIM) + c);
        float4 v1 = __ldg((const float4*)(h + (size_t)s1 * OUT_DIM) + c);
        acc.x += v0.x + v1.x; acc.y += v0.y + v1.y;
        acc.z += v0.z + v1.z; acc.w += v0.w + v1.w;
    }
    if (j < end) {
        int s0 = csr[j];
        float4 v0 = __ldg((const float4*)(h + (size_t)s0 * OUT_DIM) + c);
        acc.x += v0.x; acc.y += v0.y; acc.z += v0.z; acc.w += v0.w;
    }
    ((float4*)(agg + (size_t)node * OUT_DIM))[c] = acc;
}

// ---------------- GEMM2 fused relu: H2 = relu(A) @ W2 ----------------
__global__ __launch_bounds__(256) void gemm2_kernel(
    const float* __restrict__ A, const float* __restrict__ W2,
    float* __restrict__ H2, int M) {
    __shared__ float as[64][65];
    __shared__ float ws[64][40];
    const int base = blockIdx.x * 64;
    const int tid = threadIdx.x;

#pragma unroll
    for (int j = 0; j < 4; j++) {
        int i = tid * 4 + j;
        int r = i >> 4, cv = i & 15;
        int grow = base + r;
        float4 v = make_float4(0.f, 0.f, 0.f, 0.f);
        if (grow < M) v = *(const float4*)(A + (size_t)grow * HID_DIM + cv * 4);
        as[r][cv * 4 + 0] = fmaxf(v.x, 0.f);
        as[r][cv * 4 + 1] = fmaxf(v.y, 0.f);
        as[r][cv * 4 + 2] = fmaxf(v.z, 0.f);
        as[r][cv * 4 + 3] = fmaxf(v.w, 0.f);
    }
    for (int i = tid; i < 64 * 40; i += 256) {
        ws[i / 40][i % 40] = W2[i];
    }
    __syncthreads();

    int r = tid >> 2;
    int cseg = (tid & 3) * 10;
    float accv[10];
#pragma unroll
    for (int j = 0; j < 10; j++) accv[j] = 0.f;
#pragma unroll
    for (int k = 0; k < 64; k++) {
        float a = as[r][k];
#pragma unroll
        for (int j = 0; j < 10; j++) accv[j] = fmaf(a, ws[k][cseg + j], accv[j]);
    }
    int row = base + r;
    if (row < M) {
        float* o = H2 + (size_t)row * OUT_DIM + cseg;
#pragma unroll
        for (int j = 0; j < 10; j++) o[j] = accv[j];
    }
}

// ---------------- log_softmax: one warp per row ----------------
__global__ __launch_bounds__(256) void lsm_kernel(
    const float* __restrict__ A, float* __restrict__ out, int M) {
    int gwarp = (blockIdx.x * blockDim.x + threadIdx.x) >> 5;
    int lane = threadIdx.x & 31;
    if (gwarp >= M) return;
    const float* row = A + (size_t)gwarp * OUT_DIM;
    float e0 = row[lane];
    float e1 = (lane < 8) ? row[lane + 32] : -INFINITY;
    float m = fmaxf(e0, e1);
#pragma unroll
    for (int o = 16; o; o >>= 1) m = fmaxf(m, __shfl_xor_sync(0xFFFFFFFFu, m, o));
    float s = __expf(e0 - m) + ((lane < 8) ? __expf(e1 - m) : 0.f);
#pragma unroll
    for (int o = 16; o; o >>= 1) s += __shfl_xor_sync(0xFFFFFFFFu, s, o);
    float l = m + __logf(s);
    float* orow = out + (size_t)gwarp * OUT_DIM;
    orow[lane] = e0 - l;
    if (lane < 8) orow[lane + 32] = e1 - l;
}

// ---------------- launch ----------------
extern "C" void kernel_launch(void* const* d_in, const int* in_sizes, int n_in,
                              void* d_out, int out_size) {
    const float* x  = (const float*)d_in[0];
    const unsigned int* srcbuf = (const unsigned int*)d_in[1];
    const unsigned int* dstbuf = (const unsigned int*)d_in[2];
    const float* W1 = (const float*)d_in[3];
    const float* W2 = (const float*)d_in[4];
    float* out = (float*)d_out;

    const int M = in_sizes[0] / IN_DIM;      // 50000
    const int nE = in_sizes[1];              // 800000

    float* h1   = nullptr; cudaGetSymbolAddress((void**)&h1,   g_h1);
    float* agg1 = nullptr; cudaGetSymbolAddress((void**)&agg1, g_agg1);
    float* h2   = nullptr; cudaGetSymbolAddress((void**)&h2,   g_h2);
    float* agg2 = nullptr; cudaGetSymbolAddress((void**)&agg2, g_agg2);
    int* srci   = nullptr; cudaGetSymbolAddress((void**)&srci, g_src);
    int* dsti   = nullptr; cudaGetSymbolAddress((void**)&dsti, g_dst);
    int* csr    = nullptr; cudaGetSymbolAddress((void**)&csr,  g_csr);
    int* cnt    = nullptr; cudaGetSymbolAddress((void**)&cnt,  g_cnt);
    int* rows   = nullptr; cudaGetSymbolAddress((void**)&rows, g_rowstart);
    int* cur    = nullptr; cudaGetSymbolAddress((void**)&cur,  g_cursor);
    int* bsum   = nullptr; cudaGetSymbolAddress((void**)&bsum, g_bsum);
    int* boff   = nullptr; cudaGetSymbolAddress((void**)&boff, g_boff);

    cudaFuncSetAttribute(gemm1_tf32_kernel,
                         cudaFuncAttributeMaxDynamicSharedMemorySize, G1_SMEM_BYTES);

    // ---- CSR build ----
    detect_idx_kernel<<<1, 32>>>(srcbuf);
    zero_cnt_kernel<<<SCAN_NB, 256>>>(cnt, M);
    cvt_hist_kernel<<<(nE + 255) / 256, 256>>>(srcbuf, dstbuf, nE, srci, dsti, cnt);
    scan1_kernel<<<SCAN_NB, 256>>>(cnt, M, bsum);
    scan2_kernel<<<1, 256>>>(bsum, SCAN_NB, boff);
    scan3_kernel<<<SCAN_NB, 256>>>(cnt, M, nE, boff, rows, cur);
    fill_kernel<<<(nE + 255) / 256, 256>>>(srci, dsti, nE, cur, csr);

    // ---- GEMM1 (tf32 tensor cores) ----
    gemm1_tf32_kernel<<<(M + G1_BM - 1) / G1_BM, 256, G1_SMEM_BYTES>>>(x, W1, h1, M);

    // ---- layer-1 aggregation (gather) ----
    agg64_kernel<<<(M * 16 + 255) / 256, 256>>>(h1, rows, csr, agg1, M);

    // ---- GEMM2 (+relu) ----
    gemm2_kernel<<<(M + 63) / 64, 256>>>(agg1, W2, h2, M);

    // ---- layer-2 aggregation (gather) ----
    agg40_kernel<<<(M * 10 + 255) / 256, 256>>>(h2, rows, csr, agg2, M);

    // ---- log_softmax ----
    lsm_kernel<<<(M * 32 + 255) / 256, 256>>>(agg2, out, M);
}